// round 4
// baseline (speedup 1.0000x reference)
#include <cuda_runtime.h>
#include <cuda_bf16.h>
#include <cstdint>

#define H_IMG   64
#define W_IMG   64
#define PAD_C   10
#define LW_C    53
#define NPATCH  2809
#define MPAD    2816
#define KDIM    3072
#define NMEM    8192
#define ROWB    (KDIM * 2)        // bytes per bf16 row
#define BK      32                // K elements per stage
#define NK      (KDIM / BK)       // 96 iterations
#define STAGE_B 20480             // A(128*80) + B(128*80)
#define SROW    80                // smem row stride (bank-conflict-free for ldmatrix)
#define GEMM_SMEM (3 * STAGE_B)   // 61440
#define MARGIN  6.0f
#define BIGF    3.0e38f

// ------------------------- device scratch (static) -------------------------
__device__ __nv_bfloat16 g_Pb[(size_t)MPAD * KDIM];
__device__ float         g_Pf[(size_t)MPAD * KDIM];
__device__ __nv_bfloat16 g_Mb[(size_t)NMEM * KDIM];
__device__ float         g_msq[NMEM];
__device__ float         g_obj[(size_t)MPAD * NMEM];
__device__ int           g_row[NPATCH];
__device__ float         g_outc[3 * H_IMG * W_IMG];

// ------------------------------ PTX helpers --------------------------------
__device__ __forceinline__ uint32_t smem_u32(const void* p) {
    uint32_t a;
    asm("{ .reg .u64 t; cvta.to.shared.u64 t, %1; cvt.u32.u64 %0, t; }" : "=r"(a) : "l"(p));
    return a;
}
__device__ __forceinline__ void cpa16(uint32_t saddr, const void* gaddr) {
    asm volatile("cp.async.cg.shared.global [%0], [%1], 16;" :: "r"(saddr), "l"(gaddr));
}
#define CP_COMMIT() asm volatile("cp.async.commit_group;" ::: "memory")
#define CP_WAIT1()  asm volatile("cp.async.wait_group 1;" ::: "memory")

__device__ __forceinline__ void ldsm_x4(uint32_t a, uint32_t& r0, uint32_t& r1,
                                        uint32_t& r2, uint32_t& r3) {
    asm volatile("ldmatrix.sync.aligned.m8n8.x4.shared.b16 {%0,%1,%2,%3}, [%4];"
                 : "=r"(r0), "=r"(r1), "=r"(r2), "=r"(r3) : "r"(a));
}
__device__ __forceinline__ void mma16816(float& c0, float& c1, float& c2, float& c3,
                                         uint32_t a0, uint32_t a1, uint32_t a2, uint32_t a3,
                                         uint32_t b0, uint32_t b1) {
    asm volatile("mma.sync.aligned.m16n8k16.row.col.f32.bf16.bf16.f32 "
                 "{%0,%1,%2,%3}, {%4,%5,%6,%7}, {%8,%9}, {%0,%1,%2,%3};"
                 : "+f"(c0), "+f"(c1), "+f"(c2), "+f"(c3)
                 : "r"(a0), "r"(a1), "r"(a2), "r"(a3), "r"(b0), "r"(b1));
}

// ------------------------------ kernels ------------------------------------
__global__ void k_init() {
    int i = blockIdx.x * 1024 + threadIdx.x;
    if (i < 3 * H_IMG * W_IMG) g_outc[i] = 0.0f;
}

__global__ void k_prep_mem(const float* __restrict__ mem) {
    int j = blockIdx.x;
    const float* row = mem + (size_t)j * KDIM;
    __nv_bfloat16* brow = g_Mb + (size_t)j * KDIM;
    float s = 0.0f;
    for (int k = threadIdx.x; k < KDIM; k += 256) {
        float v = row[k];
        s += v * v;
        brow[k] = __float2bfloat16(v);
    }
    __shared__ float red[256];
    red[threadIdx.x] = s;
    __syncthreads();
    for (int o = 128; o; o >>= 1) {
        if (threadIdx.x < o) red[threadIdx.x] += red[threadIdx.x + o];
        __syncthreads();
    }
    if (threadIdx.x == 0) g_msq[j] = red[0];
}

__global__ void k_build_patches(const float* __restrict__ image) {
    int p = blockIdx.x;
    float* prow = g_Pf + (size_t)p * KDIM;
    __nv_bfloat16* brow = g_Pb + (size_t)p * KDIM;
    int ph = p / LW_C, pw = p % LW_C;
    bool valid = (p < NPATCH);
    for (int e = threadIdx.x; e < KDIM; e += 256) {
        float v = 0.0f;
        if (valid) {
            int c = e >> 10, rem = e & 1023, kh = rem >> 5, kw = rem & 31;
            int iy = ph + kh - PAD_C, ix = pw + kw - PAD_C;
            if (iy >= 0 && iy < H_IMG && ix >= 0 && ix < W_IMG)
                v = image[(iy * W_IMG + ix) * 3 + c];
        }
        prow[e] = v;
        brow[e] = __float2bfloat16(v);
    }
}

// ---- GEMM: obj[p][j] = msq[j] - 2 * <patch_p, mem_j>  (bf16 HMMA approx) ----
__global__ void __launch_bounds__(256, 2) k_gemm() {
    extern __shared__ char smem[];
    const uint32_t sb = smem_u32(smem);
    const int tid = threadIdx.x;
    const int lane = tid & 31, wid = tid >> 5;
    const int wm = wid & 1, wn = wid >> 1;          // warp grid 2(M) x 4(N)
    const int mtile = blockIdx.x, ntile = blockIdx.y;

    const char* Ag = (const char*)g_Pb + (size_t)mtile * 128 * ROWB;
    const char* Bg = (const char*)g_Mb + (size_t)ntile * 128 * ROWB;

    // per-thread cp.async chunk coords (2 chunks for A, 2 for B)
    const int c0 = tid, c1 = tid + 256;
    const int r0 = c0 >> 2, kc0 = c0 & 3;
    const int r1 = c1 >> 2, kc1 = c1 & 3;

    // per-thread ldmatrix relative offsets
    const uint32_t aRel = (uint32_t)((wm * 64 + (lane & 15)) * SROW + (lane >> 4) * 16);
    const uint32_t bRel = (uint32_t)(10240 + (wn * 32 + (lane & 15)) * SROW + (lane >> 4) * 16);

    float acc[4][4][4];
#pragma unroll
    for (int mi = 0; mi < 4; mi++)
#pragma unroll
        for (int ni = 0; ni < 4; ni++)
#pragma unroll
            for (int q = 0; q < 4; q++) acc[mi][ni][q] = 0.0f;

#define LOAD_STAGE(it)                                                               \
    do {                                                                             \
        uint32_t stoff = (uint32_t)(((it) % 3) * STAGE_B);                           \
        uint32_t kb = (uint32_t)((it) * (BK * 2));                                   \
        cpa16(sb + stoff + r0 * SROW + kc0 * 16, Ag + (size_t)r0 * ROWB + kb + kc0 * 16); \
        cpa16(sb + stoff + r1 * SROW + kc1 * 16, Ag + (size_t)r1 * ROWB + kb + kc1 * 16); \
        cpa16(sb + stoff + 10240 + r0 * SROW + kc0 * 16, Bg + (size_t)r0 * ROWB + kb + kc0 * 16); \
        cpa16(sb + stoff + 10240 + r1 * SROW + kc1 * 16, Bg + (size_t)r1 * ROWB + kb + kc1 * 16); \
    } while (0)

    LOAD_STAGE(0); CP_COMMIT();
    LOAD_STAGE(1); CP_COMMIT();

    for (int it = 0; it < NK; ++it) {
        CP_WAIT1();            // stage `it` resident
        __syncthreads();       // everyone done computing stage it-1 -> its buffer reusable
        if (it + 2 < NK) LOAD_STAGE(it + 2);
        CP_COMMIT();           // uniform group count (empty near tail)

        const uint32_t st = sb + (uint32_t)((it % 3) * STAGE_B);
#pragma unroll
        for (int ks = 0; ks < 2; ks++) {
            uint32_t a[4][4], br[2][4];
#pragma unroll
            for (int mi = 0; mi < 4; mi++)
                ldsm_x4(st + aRel + mi * (16 * SROW) + ks * 32,
                        a[mi][0], a[mi][1], a[mi][2], a[mi][3]);
#pragma unroll
            for (int np = 0; np < 2; np++)
                ldsm_x4(st + bRel + np * (16 * SROW) + ks * 32,
                        br[np][0], br[np][1], br[np][2], br[np][3]);
#pragma unroll
            for (int mi = 0; mi < 4; mi++)
#pragma unroll
                for (int ni = 0; ni < 4; ni++) {
                    int np = ni >> 1, hf = ni & 1;
                    mma16816(acc[mi][ni][0], acc[mi][ni][1], acc[mi][ni][2], acc[mi][ni][3],
                             a[mi][0], a[mi][1], a[mi][2], a[mi][3],
                             br[np][hf ? 1 : 0], br[np][hf ? 3 : 2]);
                }
        }
    }
    __syncthreads();

    // stage smem reused for msq[ntile*128 .. +128)
    float* sMsq = (float*)smem;
    if (tid < 128) sMsq[tid] = g_msq[ntile * 128 + tid];
    __syncthreads();

    const int qrow = lane >> 2, qcol = (lane & 3) * 2;
#pragma unroll
    for (int mi = 0; mi < 4; mi++) {
        int m0 = mtile * 128 + wm * 64 + mi * 16 + qrow;
#pragma unroll
        for (int ni = 0; ni < 4; ni++) {
            int nl = wn * 32 + ni * 8 + qcol;
            int n0 = ntile * 128 + nl;
            float2 v0, v1;
            v0.x = sMsq[nl]     - 2.0f * acc[mi][ni][0];
            v0.y = sMsq[nl + 1] - 2.0f * acc[mi][ni][1];
            v1.x = sMsq[nl]     - 2.0f * acc[mi][ni][2];
            v1.y = sMsq[nl + 1] - 2.0f * acc[mi][ni][3];
            *(float2*)&g_obj[(size_t)m0 * NMEM + n0]       = v0;
            *(float2*)&g_obj[(size_t)(m0 + 8) * NMEM + n0] = v1;
        }
    }
#undef LOAD_STAGE
}

// ---- exact refine: rescan row for min, collect candidates, exact fp32 dots ----
__global__ void k_refine(const float* __restrict__ mem, const int* __restrict__ mapping) {
    int p = blockIdx.x;
    __shared__ int cands[128];
    __shared__ int cnt;
    __shared__ float red[256];
    __shared__ float bestv;
    __shared__ int bestj;
    const float* orow = g_obj + (size_t)p * NMEM;

    // pass 1: row min of approx obj
    float lmin = BIGF;
    for (int j = threadIdx.x; j < NMEM; j += 256) lmin = fminf(lmin, orow[j]);
    red[threadIdx.x] = lmin;
    __syncthreads();
    for (int o = 128; o; o >>= 1) {
        if (threadIdx.x < o) red[threadIdx.x] = fminf(red[threadIdx.x], red[threadIdx.x + o]);
        __syncthreads();
    }
    float thr = red[0] + MARGIN;
    if (threadIdx.x == 0) { cnt = 0; bestv = BIGF; bestj = 0x7FFFFFFF; }
    __syncthreads();

    // pass 2: candidates within margin (L2-hot)
    for (int j = threadIdx.x; j < NMEM; j += 256) {
        if (orow[j] <= thr) {
            int pos = atomicAdd(&cnt, 1);
            if (pos < 128) cands[pos] = j;
        }
    }
    __syncthreads();
    int nc = min(cnt, 128);
    const float* prow = g_Pf + (size_t)p * KDIM;
    for (int ci = 0; ci < nc; ci++) {
        int j = cands[ci];
        const float* mrow = mem + (size_t)j * KDIM;
        float s = 0.0f;
        for (int k = threadIdx.x; k < KDIM; k += 256) s += prow[k] * mrow[k];
        red[threadIdx.x] = s;
        __syncthreads();
        for (int o = 128; o; o >>= 1) {
            if (threadIdx.x < o) red[threadIdx.x] += red[threadIdx.x + o];
            __syncthreads();
        }
        if (threadIdx.x == 0) {
            float obj = g_msq[j] - 2.0f * red[0];
            if (obj < bestv || (obj == bestv && j < bestj)) { bestv = obj; bestj = j; }
        }
        __syncthreads();
    }
    if (threadIdx.x == 0) g_row[p] = mapping[bestj];
}

__global__ void k_scatter(const float* __restrict__ mem2) {
    int p = blockIdx.x;
    int ph = p / LW_C, pw = p % LW_C;
    const float* row = mem2 + (size_t)g_row[p] * KDIM;
    for (int e = threadIdx.x; e < KDIM; e += 256) {
        int c = e >> 10, rem = e & 1023, kh = rem >> 5, kw = rem & 31;
        int y = ph + kh - PAD_C, x = pw + kw - PAD_C;
        if ((unsigned)y < 64u && (unsigned)x < 64u)
            atomicAdd(&g_outc[c * 4096 + y * 64 + x], row[e]);
    }
}

__global__ void k_final(float* __restrict__ out) {
    __shared__ float red[1024];
    int t = threadIdx.x;
    float m = -BIGF;
    for (int i = t; i < 12288; i += 1024) m = fmaxf(m, g_outc[i]);
    red[t] = m;
    __syncthreads();
    for (int o = 512; o; o >>= 1) {
        if (t < o) red[t] = fmaxf(red[t], red[t + o]);
        __syncthreads();
    }
    float mx = red[0];
    for (int i = t; i < 12288; i += 1024) {
        int c = i >> 12, rem = i & 4095, y = rem >> 6, x = rem & 63;
        out[(y * 64 + x) * 3 + c] = g_outc[i] / mx;
    }
}

// ------------------------------ launch -------------------------------------
extern "C" void kernel_launch(void* const* d_in, const int* in_sizes, int n_in,
                              void* d_out, int out_size) {
    const float* image   = (const float*)d_in[0];
    const float* mem     = (const float*)d_in[1];
    const float* mem2    = (const float*)d_in[2];
    const int*   mapping = (const int*)d_in[3];
    float* out = (float*)d_out;

    cudaFuncSetAttribute((const void*)k_gemm,
                         cudaFuncAttributeMaxDynamicSharedMemorySize, GEMM_SMEM);

    k_init<<<12, 1024>>>();
    k_prep_mem<<<NMEM, 256>>>(mem);
    k_build_patches<<<MPAD, 256>>>(image);
    dim3 gg(MPAD / 128, NMEM / 128);
    k_gemm<<<gg, 256, GEMM_SMEM>>>();
    k_refine<<<NPATCH, 256>>>(mem, mapping);
    k_scatter<<<NPATCH, 256>>>(mem2);
    k_final<<<1, 1024>>>(out);
}

// round 5
// speedup vs baseline: 1.0037x; 1.0037x over previous
#include <cuda_runtime.h>
#include <cuda_bf16.h>
#include <cstdint>

#define H_IMG   64
#define W_IMG   64
#define PAD_C   10
#define LW_C    53
#define NPATCH  2809
#define MPAD    2816
#define KDIM    3072
#define NMEM    8192
#define ROWB    (KDIM * 2)        // bytes per bf16 row
#define BK      32                // K elements per stage
#define NK      (KDIM / BK)       // 96 iterations
#define SROW    80                // smem row stride (conflict-free ldmatrix)
#define A_BYTES (128 * SROW)      // 10240
#define STAGE_B ((128 + 256) * SROW)  // 30720
#define NSTAGE  4
#define GEMM_SMEM (NSTAGE * STAGE_B)  // 122880
#define MARGIN  6.0f
#define BIGF    3.0e38f

// ------------------------- device scratch (static) -------------------------
__device__ __nv_bfloat16 g_Pb[(size_t)MPAD * KDIM];
__device__ float         g_Pf[(size_t)MPAD * KDIM];
__device__ __nv_bfloat16 g_Mb[(size_t)NMEM * KDIM];
__device__ float         g_msq[NMEM];
__device__ float         g_obj[(size_t)MPAD * NMEM];
__device__ int           g_row[NPATCH];
__device__ float         g_outc[3 * H_IMG * W_IMG];

// ------------------------------ PTX helpers --------------------------------
__device__ __forceinline__ uint32_t smem_u32(const void* p) {
    uint32_t a;
    asm("{ .reg .u64 t; cvta.to.shared.u64 t, %1; cvt.u32.u64 %0, t; }" : "=r"(a) : "l"(p));
    return a;
}
__device__ __forceinline__ void cpa16(uint32_t saddr, const void* gaddr) {
    asm volatile("cp.async.cg.shared.global [%0], [%1], 16;" :: "r"(saddr), "l"(gaddr));
}
#define CP_COMMIT() asm volatile("cp.async.commit_group;" ::: "memory")
#define CP_WAIT2()  asm volatile("cp.async.wait_group 2;" ::: "memory")

__device__ __forceinline__ void ldsm_x4(uint32_t a, uint32_t& r0, uint32_t& r1,
                                        uint32_t& r2, uint32_t& r3) {
    asm volatile("ldmatrix.sync.aligned.m8n8.x4.shared.b16 {%0,%1,%2,%3}, [%4];"
                 : "=r"(r0), "=r"(r1), "=r"(r2), "=r"(r3) : "r"(a));
}
__device__ __forceinline__ void mma16816(float& c0, float& c1, float& c2, float& c3,
                                         uint32_t a0, uint32_t a1, uint32_t a2, uint32_t a3,
                                         uint32_t b0, uint32_t b1) {
    asm volatile("mma.sync.aligned.m16n8k16.row.col.f32.bf16.bf16.f32 "
                 "{%0,%1,%2,%3}, {%4,%5,%6,%7}, {%8,%9}, {%0,%1,%2,%3};"
                 : "+f"(c0), "+f"(c1), "+f"(c2), "+f"(c3)
                 : "r"(a0), "r"(a1), "r"(a2), "r"(a3), "r"(b0), "r"(b1));
}

// ------------------------------ kernels ------------------------------------
__global__ void k_init() {
    int i = blockIdx.x * 1024 + threadIdx.x;
    if (i < 3 * H_IMG * W_IMG) g_outc[i] = 0.0f;
}

__global__ void k_prep_mem(const float* __restrict__ mem) {
    int j = blockIdx.x;
    const float* row = mem + (size_t)j * KDIM;
    __nv_bfloat16* brow = g_Mb + (size_t)j * KDIM;
    float s = 0.0f;
    for (int k = threadIdx.x; k < KDIM; k += 256) {
        float v = row[k];
        s += v * v;
        brow[k] = __float2bfloat16(v);
    }
    __shared__ float red[256];
    red[threadIdx.x] = s;
    __syncthreads();
    for (int o = 128; o; o >>= 1) {
        if (threadIdx.x < o) red[threadIdx.x] += red[threadIdx.x + o];
        __syncthreads();
    }
    if (threadIdx.x == 0) g_msq[j] = red[0];
}

__global__ void k_build_patches(const float* __restrict__ image) {
    int p = blockIdx.x;
    float* prow = g_Pf + (size_t)p * KDIM;
    __nv_bfloat16* brow = g_Pb + (size_t)p * KDIM;
    int ph = p / LW_C, pw = p % LW_C;
    bool valid = (p < NPATCH);
    for (int e = threadIdx.x; e < KDIM; e += 256) {
        float v = 0.0f;
        if (valid) {
            int c = e >> 10, rem = e & 1023, kh = rem >> 5, kw = rem & 31;
            int iy = ph + kh - PAD_C, ix = pw + kw - PAD_C;
            if (iy >= 0 && iy < H_IMG && ix >= 0 && ix < W_IMG)
                v = image[(iy * W_IMG + ix) * 3 + c];
        }
        prow[e] = v;
        brow[e] = __float2bfloat16(v);
    }
}

// ---- GEMM: obj[p][j] = msq[j] - 2 * <patch_p, mem_j>  (bf16 HMMA approx) ----
// CTA tile 128x256x32, warp tile 64x64, 8 warps (2M x 4N), 4-stage cp.async.
__global__ void __launch_bounds__(256, 1) k_gemm() {
    extern __shared__ char smem[];
    const uint32_t sb = smem_u32(smem);
    const int tid = threadIdx.x;
    const int lane = tid & 31, wid = tid >> 5;
    const int wm = wid & 1, wn = wid >> 1;          // 2(M) x 4(N)
    const int mtile = blockIdx.x, ntile = blockIdx.y;

    const char* Ag = (const char*)g_Pb + (size_t)mtile * 128 * ROWB;
    const char* Bg = (const char*)g_Mb + (size_t)ntile * 256 * ROWB;

    // cp.async mapping: A 512 chunks (2/thread), B 1024 chunks (4/thread)
    const int ra0 = tid >> 2,            ka0 = (tid & 3) * 16;
    const int ra1 = (tid + 256) >> 2,    ka1 = ka0;
    const int rb0 = tid >> 2,            kb0 = ka0;
    const int rb1 = (tid + 256) >> 2;
    const int rb2 = (tid + 512) >> 2;
    const int rb3 = (tid + 768) >> 2;

    // ldmatrix relative offsets (within a stage)
    const uint32_t aRel = (uint32_t)((wm * 64 + (lane & 15)) * SROW + (lane >> 4) * 16);
    const uint32_t bRel = (uint32_t)(A_BYTES + (wn * 64 + (lane & 15)) * SROW + (lane >> 4) * 16);

    float acc[4][8][4];
#pragma unroll
    for (int mi = 0; mi < 4; mi++)
#pragma unroll
        for (int ni = 0; ni < 8; ni++)
#pragma unroll
            for (int q = 0; q < 4; q++) acc[mi][ni][q] = 0.0f;

#define LOAD_STAGE(it)                                                                 \
    do {                                                                               \
        uint32_t so = (uint32_t)(((it) & 3) * STAGE_B);                                \
        uint32_t kb = (uint32_t)((it) * (BK * 2));                                     \
        cpa16(sb + so + ra0 * SROW + ka0,            Ag + (size_t)ra0 * ROWB + kb + ka0); \
        cpa16(sb + so + ra1 * SROW + ka1,            Ag + (size_t)ra1 * ROWB + kb + ka1); \
        cpa16(sb + so + A_BYTES + rb0 * SROW + kb0,  Bg + (size_t)rb0 * ROWB + kb + kb0); \
        cpa16(sb + so + A_BYTES + rb1 * SROW + kb0,  Bg + (size_t)rb1 * ROWB + kb + kb0); \
        cpa16(sb + so + A_BYTES + rb2 * SROW + kb0,  Bg + (size_t)rb2 * ROWB + kb + kb0); \
        cpa16(sb + so + A_BYTES + rb3 * SROW + kb0,  Bg + (size_t)rb3 * ROWB + kb + kb0); \
    } while (0)

    LOAD_STAGE(0); CP_COMMIT();
    LOAD_STAGE(1); CP_COMMIT();
    LOAD_STAGE(2); CP_COMMIT();

    for (int it = 0; it < NK; ++it) {
        CP_WAIT2();            // stage `it` resident (<=2 younger groups pending)
        __syncthreads();       // all warps done reading stage it-1 -> (it+3)&3 reusable
        if (it + 3 < NK) LOAD_STAGE(it + 3);
        CP_COMMIT();           // uniform group count (empty near tail)

        const uint32_t st = sb + (uint32_t)((it & 3) * STAGE_B);
#pragma unroll
        for (int ks = 0; ks < 2; ks++) {
            uint32_t a[4][4], b[4][4];
#pragma unroll
            for (int mi = 0; mi < 4; mi++)
                ldsm_x4(st + aRel + mi * (16 * SROW) + ks * 32,
                        a[mi][0], a[mi][1], a[mi][2], a[mi][3]);
#pragma unroll
            for (int np = 0; np < 4; np++)
                ldsm_x4(st + bRel + np * (16 * SROW) + ks * 32,
                        b[np][0], b[np][1], b[np][2], b[np][3]);
#pragma unroll
            for (int mi = 0; mi < 4; mi++)
#pragma unroll
                for (int ni = 0; ni < 8; ni++) {
                    int np = ni >> 1, hf = ni & 1;
                    mma16816(acc[mi][ni][0], acc[mi][ni][1], acc[mi][ni][2], acc[mi][ni][3],
                             a[mi][0], a[mi][1], a[mi][2], a[mi][3],
                             b[np][hf], b[np][2 + hf]);
                }
        }
    }
    __syncthreads();

    // stage smem reused for msq[ntile*256 .. +256)
    float* sMsq = (float*)smem;
    sMsq[tid] = g_msq[ntile * 256 + tid];
    __syncthreads();

    const int qrow = lane >> 2, qcol = (lane & 3) * 2;
#pragma unroll
    for (int mi = 0; mi < 4; mi++) {
        int m0 = mtile * 128 + wm * 64 + mi * 16 + qrow;
#pragma unroll
        for (int ni = 0; ni < 8; ni++) {
            int nl = wn * 64 + ni * 8 + qcol;
            int n0 = ntile * 256 + nl;
            float2 v0, v1;
            v0.x = sMsq[nl]     - 2.0f * acc[mi][ni][0];
            v0.y = sMsq[nl + 1] - 2.0f * acc[mi][ni][1];
            v1.x = sMsq[nl]     - 2.0f * acc[mi][ni][2];
            v1.y = sMsq[nl + 1] - 2.0f * acc[mi][ni][3];
            *(float2*)&g_obj[(size_t)m0 * NMEM + n0]       = v0;
            *(float2*)&g_obj[(size_t)(m0 + 8) * NMEM + n0] = v1;
        }
    }
#undef LOAD_STAGE
}

// ---- exact refine: row min, candidates within margin, exact fp32 dots ----
__global__ void k_refine(const float* __restrict__ mem, const int* __restrict__ mapping) {
    int p = blockIdx.x;
    __shared__ int cands[128];
    __shared__ int cnt;
    __shared__ float red[256];
    __shared__ float bestv;
    __shared__ int bestj;
    const float* orow = g_obj + (size_t)p * NMEM;

    float lmin = BIGF;
    for (int j = threadIdx.x; j < NMEM; j += 256) lmin = fminf(lmin, orow[j]);
    red[threadIdx.x] = lmin;
    __syncthreads();
    for (int o = 128; o; o >>= 1) {
        if (threadIdx.x < o) red[threadIdx.x] = fminf(red[threadIdx.x], red[threadIdx.x + o]);
        __syncthreads();
    }
    float thr = red[0] + MARGIN;
    if (threadIdx.x == 0) { cnt = 0; bestv = BIGF; bestj = 0x7FFFFFFF; }
    __syncthreads();

    for (int j = threadIdx.x; j < NMEM; j += 256) {
        if (orow[j] <= thr) {
            int pos = atomicAdd(&cnt, 1);
            if (pos < 128) cands[pos] = j;
        }
    }
    __syncthreads();
    int nc = min(cnt, 128);
    const float* prow = g_Pf + (size_t)p * KDIM;
    for (int ci = 0; ci < nc; ci++) {
        int j = cands[ci];
        const float* mrow = mem + (size_t)j * KDIM;
        float s = 0.0f;
        for (int k = threadIdx.x; k < KDIM; k += 256) s += prow[k] * mrow[k];
        red[threadIdx.x] = s;
        __syncthreads();
        for (int o = 128; o; o >>= 1) {
            if (threadIdx.x < o) red[threadIdx.x] += red[threadIdx.x + o];
            __syncthreads();
        }
        if (threadIdx.x == 0) {
            float obj = g_msq[j] - 2.0f * red[0];
            if (obj < bestv || (obj == bestv && j < bestj)) { bestv = obj; bestj = j; }
        }
        __syncthreads();
    }
    if (threadIdx.x == 0) g_row[p] = mapping[bestj];
}

__global__ void k_scatter(const float* __restrict__ mem2) {
    int p = blockIdx.x;
    int ph = p / LW_C, pw = p % LW_C;
    const float* row = mem2 + (size_t)g_row[p] * KDIM;
    for (int e = threadIdx.x; e < KDIM; e += 256) {
        int c = e >> 10, rem = e & 1023, kh = rem >> 5, kw = rem & 31;
        int y = ph + kh - PAD_C, x = pw + kw - PAD_C;
        if ((unsigned)y < 64u && (unsigned)x < 64u)
            atomicAdd(&g_outc[c * 4096 + y * 64 + x], row[e]);
    }
}

__global__ void k_final(float* __restrict__ out) {
    __shared__ float red[1024];
    int t = threadIdx.x;
    float m = -BIGF;
    for (int i = t; i < 12288; i += 1024) m = fmaxf(m, g_outc[i]);
    red[t] = m;
    __syncthreads();
    for (int o = 512; o; o >>= 1) {
        if (t < o) red[t] = fmaxf(red[t], red[t + o]);
        __syncthreads();
    }
    float mx = red[0];
    for (int i = t; i < 12288; i += 1024) {
        int c = i >> 12, rem = i & 4095, y = rem >> 6, x = rem & 63;
        out[(y * 64 + x) * 3 + c] = g_outc[i] / mx;
    }
}

// ------------------------------ launch -------------------------------------
extern "C" void kernel_launch(void* const* d_in, const int* in_sizes, int n_in,
                              void* d_out, int out_size) {
    const float* image   = (const float*)d_in[0];
    const float* mem     = (const float*)d_in[1];
    const float* mem2    = (const float*)d_in[2];
    const int*   mapping = (const int*)d_in[3];
    float* out = (float*)d_out;

    cudaFuncSetAttribute((const void*)k_gemm,
                         cudaFuncAttributeMaxDynamicSharedMemorySize, GEMM_SMEM);

    k_init<<<12, 1024>>>();
    k_prep_mem<<<NMEM, 256>>>(mem);
    k_build_patches<<<MPAD, 256>>>(image);
    dim3 gg(MPAD / 128, NMEM / 256);
    k_gemm<<<gg, 256, GEMM_SMEM>>>();
    k_refine<<<NPATCH, 256>>>(mem, mapping);
    k_scatter<<<NPATCH, 256>>>(mem2);
    k_final<<<1, 1024>>>(out);
}

// round 6
// speedup vs baseline: 1.5338x; 1.5282x over previous
#include <cuda_runtime.h>
#include <cuda_bf16.h>
#include <cstdint>

#define H_IMG   64
#define W_IMG   64
#define PAD_C   10
#define LW_C    53
#define NPATCH  2809
#define MPAD    2816
#define KDIM    3072
#define NMEM    8192
#define ROWB    KDIM              // bytes per int8 row
#define BK      64                // K int8 elements per stage (64 B per row-chunk)
#define NK      (KDIM / BK)       // 48 iterations
#define SROW    80                // smem row stride (conflict-free ldmatrix)
#define A_BYTES (128 * SROW)      // 10240
#define STAGE_B ((128 + 256) * SROW)  // 30720
#define NSTAGE  4
#define GEMM_SMEM (NSTAGE * STAGE_B)  // 122880
#define MARGIN  12.0f
#define BIGF    3.0e38f

// ------------------------- device scratch (static) -------------------------
__device__ int8_t g_Pq[(size_t)MPAD * KDIM];
__device__ float  g_Pf[(size_t)MPAD * KDIM];
__device__ int8_t g_Mq[(size_t)NMEM * KDIM];
__device__ float  g_msq[NMEM];
__device__ float  g_msc[NMEM];    // mem row dequant scale
__device__ float  g_psc[MPAD];    // patch row dequant scale
__device__ float  g_obj[(size_t)MPAD * NMEM];
__device__ int    g_row[NPATCH];
__device__ float  g_outc[3 * H_IMG * W_IMG];

// ------------------------------ PTX helpers --------------------------------
__device__ __forceinline__ uint32_t smem_u32(const void* p) {
    uint32_t a;
    asm("{ .reg .u64 t; cvta.to.shared.u64 t, %1; cvt.u32.u64 %0, t; }" : "=r"(a) : "l"(p));
    return a;
}
__device__ __forceinline__ void cpa16(uint32_t saddr, const void* gaddr) {
    asm volatile("cp.async.cg.shared.global [%0], [%1], 16;" :: "r"(saddr), "l"(gaddr));
}
#define CP_COMMIT() asm volatile("cp.async.commit_group;" ::: "memory")
#define CP_WAIT2()  asm volatile("cp.async.wait_group 2;" ::: "memory")

__device__ __forceinline__ void ldsm_x4(uint32_t a, uint32_t& r0, uint32_t& r1,
                                        uint32_t& r2, uint32_t& r3) {
    asm volatile("ldmatrix.sync.aligned.m8n8.x4.shared.b16 {%0,%1,%2,%3}, [%4];"
                 : "=r"(r0), "=r"(r1), "=r"(r2), "=r"(r3) : "r"(a));
}
__device__ __forceinline__ void mma_s8(int& c0, int& c1, int& c2, int& c3,
                                       uint32_t a0, uint32_t a1, uint32_t a2, uint32_t a3,
                                       uint32_t b0, uint32_t b1) {
    asm volatile("mma.sync.aligned.m16n8k32.row.col.s32.s8.s8.s32 "
                 "{%0,%1,%2,%3}, {%4,%5,%6,%7}, {%8,%9}, {%0,%1,%2,%3};"
                 : "+r"(c0), "+r"(c1), "+r"(c2), "+r"(c3)
                 : "r"(a0), "r"(a1), "r"(a2), "r"(a3), "r"(b0), "r"(b1));
}

// ------------------------------ kernels ------------------------------------
__global__ void k_init() {
    int i = blockIdx.x * 1024 + threadIdx.x;
    if (i < 3 * H_IMG * W_IMG) g_outc[i] = 0.0f;
}

// mem row -> int8 + exact fp32 sumsq + scale (smem-staged, one global read)
__global__ void k_prep_mem(const float* __restrict__ mem) {
    int j = blockIdx.x;
    __shared__ float srow[KDIM];
    __shared__ float red[256];
    __shared__ float redm[256];
    const float* row = mem + (size_t)j * KDIM;
    float s = 0.0f, mx = 0.0f;
    for (int k = threadIdx.x; k < KDIM; k += 256) {
        float v = row[k];
        srow[k] = v;
        s += v * v;
        mx = fmaxf(mx, fabsf(v));
    }
    red[threadIdx.x] = s;
    redm[threadIdx.x] = mx;
    __syncthreads();
    for (int o = 128; o; o >>= 1) {
        if (threadIdx.x < o) {
            red[threadIdx.x] += red[threadIdx.x + o];
            redm[threadIdx.x] = fmaxf(redm[threadIdx.x], redm[threadIdx.x + o]);
        }
        __syncthreads();
    }
    float mabs = redm[0];
    float inv = (mabs > 0.0f) ? (127.0f / mabs) : 0.0f;
    if (threadIdx.x == 0) { g_msq[j] = red[0]; g_msc[j] = mabs / 127.0f; }
    int8_t* qrow = g_Mq + (size_t)j * KDIM;
    for (int k = threadIdx.x; k < KDIM; k += 256) {
        int q = __float2int_rn(srow[k] * inv);
        qrow[k] = (int8_t)max(-127, min(127, q));
    }
}

// patch row -> fp32 (for refine) + int8 + scale
__global__ void k_build_patches(const float* __restrict__ image) {
    int p = blockIdx.x;
    __shared__ float srow[KDIM];
    __shared__ float redm[256];
    float* prow = g_Pf + (size_t)p * KDIM;
    int8_t* qrow = g_Pq + (size_t)p * KDIM;
    int ph = p / LW_C, pw = p % LW_C;
    bool valid = (p < NPATCH);
    float mx = 0.0f;
    for (int e = threadIdx.x; e < KDIM; e += 256) {
        float v = 0.0f;
        if (valid) {
            int c = e >> 10, rem = e & 1023, kh = rem >> 5, kw = rem & 31;
            int iy = ph + kh - PAD_C, ix = pw + kw - PAD_C;
            if (iy >= 0 && iy < H_IMG && ix >= 0 && ix < W_IMG)
                v = image[(iy * W_IMG + ix) * 3 + c];
        }
        srow[e] = v;
        prow[e] = v;
        mx = fmaxf(mx, fabsf(v));
    }
    redm[threadIdx.x] = mx;
    __syncthreads();
    for (int o = 128; o; o >>= 1) {
        if (threadIdx.x < o) redm[threadIdx.x] = fmaxf(redm[threadIdx.x], redm[threadIdx.x + o]);
        __syncthreads();
    }
    float mabs = redm[0];
    float inv = (mabs > 0.0f) ? (127.0f / mabs) : 0.0f;
    if (threadIdx.x == 0) g_psc[p] = mabs / 127.0f;
    for (int e = threadIdx.x; e < KDIM; e += 256) {
        int q = __float2int_rn(srow[e] * inv);
        qrow[e] = (int8_t)max(-127, min(127, q));
    }
}

// ---- GEMM: obj[p][j] = msq[j] - 2*sp*sj*<q_p, q_j>  (int8 IMMA approx) ----
// CTA tile 128x256x64(int8), warp tile 64x64, 8 warps (2M x 4N), 4-stage cp.async.
__global__ void __launch_bounds__(256, 1) k_gemm() {
    extern __shared__ char smem[];
    const uint32_t sb = smem_u32(smem);
    const int tid = threadIdx.x;
    const int lane = tid & 31, wid = tid >> 5;
    const int wm = wid & 1, wn = wid >> 1;          // 2(M) x 4(N)
    const int mtile = blockIdx.x, ntile = blockIdx.y;

    const char* Ag = (const char*)g_Pq + (size_t)mtile * 128 * ROWB;
    const char* Bg = (const char*)g_Mq + (size_t)ntile * 256 * ROWB;

    // cp.async: 64 B per row per stage = 4 chunks/row. A 512 chunks (2/thr), B 1024 (4/thr)
    const int ra0 = tid >> 2,         ka0 = (tid & 3) * 16;
    const int ra1 = (tid + 256) >> 2;
    const int rb1 = (tid + 256) >> 2;
    const int rb2 = (tid + 512) >> 2;
    const int rb3 = (tid + 768) >> 2;

    const uint32_t aRel = (uint32_t)((wm * 64 + (lane & 15)) * SROW + (lane >> 4) * 16);
    const uint32_t bRel = (uint32_t)(A_BYTES + (wn * 64 + (lane & 15)) * SROW + (lane >> 4) * 16);

    int acc[4][8][4];
#pragma unroll
    for (int mi = 0; mi < 4; mi++)
#pragma unroll
        for (int ni = 0; ni < 8; ni++)
#pragma unroll
            for (int q = 0; q < 4; q++) acc[mi][ni][q] = 0;

#define LOAD_STAGE(it)                                                                 \
    do {                                                                               \
        uint32_t so = (uint32_t)(((it) & 3) * STAGE_B);                                \
        uint32_t kb = (uint32_t)((it) * BK);                                           \
        cpa16(sb + so + ra0 * SROW + ka0,           Ag + (size_t)ra0 * ROWB + kb + ka0); \
        cpa16(sb + so + ra1 * SROW + ka0,           Ag + (size_t)ra1 * ROWB + kb + ka0); \
        cpa16(sb + so + A_BYTES + ra0 * SROW + ka0, Bg + (size_t)ra0 * ROWB + kb + ka0); \
        cpa16(sb + so + A_BYTES + rb1 * SROW + ka0, Bg + (size_t)rb1 * ROWB + kb + ka0); \
        cpa16(sb + so + A_BYTES + rb2 * SROW + ka0, Bg + (size_t)rb2 * ROWB + kb + ka0); \
        cpa16(sb + so + A_BYTES + rb3 * SROW + ka0, Bg + (size_t)rb3 * ROWB + kb + ka0); \
    } while (0)

    LOAD_STAGE(0); CP_COMMIT();
    LOAD_STAGE(1); CP_COMMIT();
    LOAD_STAGE(2); CP_COMMIT();

    for (int it = 0; it < NK; ++it) {
        CP_WAIT2();
        __syncthreads();
        if (it + 3 < NK) LOAD_STAGE(it + 3);
        CP_COMMIT();

        const uint32_t st = sb + (uint32_t)((it & 3) * STAGE_B);
#pragma unroll
        for (int ks = 0; ks < 2; ks++) {            // two k32 int8 groups (32 B each)
            uint32_t a[4][4], b[4][4];
#pragma unroll
            for (int mi = 0; mi < 4; mi++)
                ldsm_x4(st + aRel + mi * (16 * SROW) + ks * 32,
                        a[mi][0], a[mi][1], a[mi][2], a[mi][3]);
#pragma unroll
            for (int np = 0; np < 4; np++)
                ldsm_x4(st + bRel + np * (16 * SROW) + ks * 32,
                        b[np][0], b[np][1], b[np][2], b[np][3]);
#pragma unroll
            for (int mi = 0; mi < 4; mi++)
#pragma unroll
                for (int ni = 0; ni < 8; ni++) {
                    int np = ni >> 1, hf = ni & 1;
                    mma_s8(acc[mi][ni][0], acc[mi][ni][1], acc[mi][ni][2], acc[mi][ni][3],
                           a[mi][0], a[mi][1], a[mi][2], a[mi][3],
                           b[np][hf], b[np][2 + hf]);
                }
        }
    }
    __syncthreads();

    // stage smem reused: msq[256] + msc[256] for this ntile
    float* sMsq = (float*)smem;
    float* sMsc = (float*)smem + 256;
    sMsq[tid] = g_msq[ntile * 256 + tid];
    sMsc[tid] = g_msc[ntile * 256 + tid];
    __syncthreads();

    const int qrow = lane >> 2, qcol = (lane & 3) * 2;
#pragma unroll
    for (int mi = 0; mi < 4; mi++) {
        int m0 = mtile * 128 + wm * 64 + mi * 16 + qrow;
        float sp0 = 2.0f * g_psc[m0];
        float sp8 = 2.0f * g_psc[m0 + 8];
#pragma unroll
        for (int ni = 0; ni < 8; ni++) {
            int nl = wn * 64 + ni * 8 + qcol;
            int n0 = ntile * 256 + nl;
            float sj0 = sMsc[nl], sj1 = sMsc[nl + 1];
            float2 v0, v1;
            v0.x = sMsq[nl]     - sp0 * sj0 * (float)acc[mi][ni][0];
            v0.y = sMsq[nl + 1] - sp0 * sj1 * (float)acc[mi][ni][1];
            v1.x = sMsq[nl]     - sp8 * sj0 * (float)acc[mi][ni][2];
            v1.y = sMsq[nl + 1] - sp8 * sj1 * (float)acc[mi][ni][3];
            *(float2*)&g_obj[(size_t)m0 * NMEM + n0]       = v0;
            *(float2*)&g_obj[(size_t)(m0 + 8) * NMEM + n0] = v1;
        }
    }
#undef LOAD_STAGE
}

// ---- exact refine: row min, candidates within margin, exact fp32 dots ----
__global__ void k_refine(const float* __restrict__ mem, const int* __restrict__ mapping) {
    int p = blockIdx.x;
    __shared__ int cands[128];
    __shared__ int cnt;
    __shared__ float red[256];
    __shared__ float bestv;
    __shared__ int bestj;
    const float* orow = g_obj + (size_t)p * NMEM;

    float lmin = BIGF;
    for (int j = threadIdx.x; j < NMEM; j += 256) lmin = fminf(lmin, orow[j]);
    red[threadIdx.x] = lmin;
    __syncthreads();
    for (int o = 128; o; o >>= 1) {
        if (threadIdx.x < o) red[threadIdx.x] = fminf(red[threadIdx.x], red[threadIdx.x + o]);
        __syncthreads();
    }
    float thr = red[0] + MARGIN;
    if (threadIdx.x == 0) { cnt = 0; bestv = BIGF; bestj = 0x7FFFFFFF; }
    __syncthreads();

    for (int j = threadIdx.x; j < NMEM; j += 256) {
        if (orow[j] <= thr) {
            int pos = atomicAdd(&cnt, 1);
            if (pos < 128) cands[pos] = j;
        }
    }
    __syncthreads();
    int nc = min(cnt, 128);
    const float* prow = g_Pf + (size_t)p * KDIM;
    for (int ci = 0; ci < nc; ci++) {
        int j = cands[ci];
        const float* mrow = mem + (size_t)j * KDIM;
        float s = 0.0f;
        for (int k = threadIdx.x; k < KDIM; k += 256) s += prow[k] * mrow[k];
        red[threadIdx.x] = s;
        __syncthreads();
        for (int o = 128; o; o >>= 1) {
            if (threadIdx.x < o) red[threadIdx.x] += red[threadIdx.x + o];
            __syncthreads();
        }
        if (threadIdx.x == 0) {
            float obj = g_msq[j] - 2.0f * red[0];
            if (obj < bestv || (obj == bestv && j < bestj)) { bestv = obj; bestj = j; }
        }
        __syncthreads();
    }
    if (threadIdx.x == 0) g_row[p] = mapping[bestj];
}

__global__ void k_scatter(const float* __restrict__ mem2) {
    int p = blockIdx.x;
    int ph = p / LW_C, pw = p % LW_C;
    const float* row = mem2 + (size_t)g_row[p] * KDIM;
    for (int e = threadIdx.x; e < KDIM; e += 256) {
        int c = e >> 10, rem = e & 1023, kh = rem >> 5, kw = rem & 31;
        int y = ph + kh - PAD_C, x = pw + kw - PAD_C;
        if ((unsigned)y < 64u && (unsigned)x < 64u)
            atomicAdd(&g_outc[c * 4096 + y * 64 + x], row[e]);
    }
}

__global__ void k_final(float* __restrict__ out) {
    __shared__ float red[1024];
    int t = threadIdx.x;
    float m = -BIGF;
    for (int i = t; i < 12288; i += 1024) m = fmaxf(m, g_outc[i]);
    red[t] = m;
    __syncthreads();
    for (int o = 512; o; o >>= 1) {
        if (t < o) red[t] = fmaxf(red[t], red[t + o]);
        __syncthreads();
    }
    float mx = red[0];
    for (int i = t; i < 12288; i += 1024) {
        int c = i >> 12, rem = i & 4095, y = rem >> 6, x = rem & 63;
        out[(y * 64 + x) * 3 + c] = g_outc[i] / mx;
    }
}

// ------------------------------ launch -------------------------------------
extern "C" void kernel_launch(void* const* d_in, const int* in_sizes, int n_in,
                              void* d_out, int out_size) {
    const float* image   = (const float*)d_in[0];
    const float* mem     = (const float*)d_in[1];
    const float* mem2    = (const float*)d_in[2];
    const int*   mapping = (const int*)d_in[3];
    float* out = (float*)d_out;

    cudaFuncSetAttribute((const void*)k_gemm,
                         cudaFuncAttributeMaxDynamicSharedMemorySize, GEMM_SMEM);

    k_init<<<12, 1024>>>();
    k_prep_mem<<<NMEM, 256>>>(mem);
    k_build_patches<<<MPAD, 256>>>(image);
    dim3 gg(MPAD / 128, NMEM / 256);
    k_gemm<<<gg, 256, GEMM_SMEM>>>();
    k_refine<<<NPATCH, 256>>>(mem, mapping);
    k_scatter<<<NPATCH, 256>>>(mem2);
    k_final<<<1, 1024>>>(out);
}

// round 7
// speedup vs baseline: 1.7577x; 1.1460x over previous
#include <cuda_runtime.h>
#include <cuda_bf16.h>
#include <cstdint>

#define H_IMG   64
#define W_IMG   64
#define PAD_C   10
#define LW_C    53
#define NPATCH  2809
#define MPAD    2816
#define KDIM    3072
#define NMEM    8192
#define ROWB    KDIM              // bytes per int8 row
#define BK      128               // K int8 elements per stage (128 B per row)
#define NK      (KDIM / BK)       // 24 iterations
#define A_SZ    16384             // 128 rows * 128 B
#define STAGE_B 49152             // (128 + 256) rows * 128 B
#define NSTAGE  3
#define GEMM_SMEM (NSTAGE * STAGE_B)  // 147456
#define MARGIN  12.0f
#define BIGF    3.0e38f

// ------------------------- device scratch (static) -------------------------
__device__ int8_t   g_Pq[(size_t)MPAD * KDIM];
__device__ float    g_Pf[(size_t)MPAD * KDIM];
__device__ int8_t   g_Mq[(size_t)NMEM * KDIM];
__device__ float    g_msq[NMEM];
__device__ float    g_msc[NMEM];
__device__ float    g_psc[MPAD];
__device__ float    g_obj[(size_t)MPAD * NMEM];
__device__ unsigned g_min[MPAD];
__device__ int      g_row[NPATCH];
__device__ float    g_outc[3 * H_IMG * W_IMG];

// ------------------------------ PTX helpers --------------------------------
__device__ __forceinline__ uint32_t smem_u32(const void* p) {
    uint32_t a;
    asm("{ .reg .u64 t; cvta.to.shared.u64 t, %1; cvt.u32.u64 %0, t; }" : "=r"(a) : "l"(p));
    return a;
}
__device__ __forceinline__ void cpa16(uint32_t saddr, const void* gaddr) {
    asm volatile("cp.async.cg.shared.global [%0], [%1], 16;" :: "r"(saddr), "l"(gaddr));
}
#define CP_COMMIT() asm volatile("cp.async.commit_group;" ::: "memory")
#define CP_WAIT1()  asm volatile("cp.async.wait_group 1;" ::: "memory")

__device__ __forceinline__ void ldsm_x4(uint32_t a, uint32_t& r0, uint32_t& r1,
                                        uint32_t& r2, uint32_t& r3) {
    asm volatile("ldmatrix.sync.aligned.m8n8.x4.shared.b16 {%0,%1,%2,%3}, [%4];"
                 : "=r"(r0), "=r"(r1), "=r"(r2), "=r"(r3) : "r"(a));
}
__device__ __forceinline__ void mma_s8(int& c0, int& c1, int& c2, int& c3,
                                       uint32_t a0, uint32_t a1, uint32_t a2, uint32_t a3,
                                       uint32_t b0, uint32_t b1) {
    asm volatile("mma.sync.aligned.m16n8k32.row.col.s32.s8.s8.s32 "
                 "{%0,%1,%2,%3}, {%4,%5,%6,%7}, {%8,%9}, {%0,%1,%2,%3};"
                 : "+r"(c0), "+r"(c1), "+r"(c2), "+r"(c3)
                 : "r"(a0), "r"(a1), "r"(a2), "r"(a3), "r"(b0), "r"(b1));
}
__device__ __forceinline__ unsigned fkey(float f) {
    unsigned u = __float_as_uint(f);
    return (u & 0x80000000u) ? ~u : (u | 0x80000000u);
}
__device__ __forceinline__ float funkey(unsigned k) {
    unsigned u = (k & 0x80000000u) ? (k & 0x7FFFFFFFu) : ~k;
    return __uint_as_float(u);
}

// ------------------------------ kernels ------------------------------------
__global__ void k_init() {
    int i = blockIdx.x * 1024 + threadIdx.x;
    if (i < 3 * H_IMG * W_IMG) g_outc[i] = 0.0f;
    if (i < MPAD) g_min[i] = 0xFFFFFFFFu;
}

__global__ void k_prep_mem(const float* __restrict__ mem) {
    int j = blockIdx.x;
    __shared__ float srow[KDIM];
    __shared__ float red[256];
    __shared__ float redm[256];
    const float* row = mem + (size_t)j * KDIM;
    float s = 0.0f, mx = 0.0f;
    for (int k = threadIdx.x; k < KDIM; k += 256) {
        float v = row[k];
        srow[k] = v;
        s += v * v;
        mx = fmaxf(mx, fabsf(v));
    }
    red[threadIdx.x] = s;
    redm[threadIdx.x] = mx;
    __syncthreads();
    for (int o = 128; o; o >>= 1) {
        if (threadIdx.x < o) {
            red[threadIdx.x] += red[threadIdx.x + o];
            redm[threadIdx.x] = fmaxf(redm[threadIdx.x], redm[threadIdx.x + o]);
        }
        __syncthreads();
    }
    float mabs = redm[0];
    float inv = (mabs > 0.0f) ? (127.0f / mabs) : 0.0f;
    if (threadIdx.x == 0) { g_msq[j] = red[0]; g_msc[j] = mabs / 127.0f; }
    int8_t* qrow = g_Mq + (size_t)j * KDIM;
    for (int k = threadIdx.x; k < KDIM; k += 256) {
        int q = __float2int_rn(srow[k] * inv);
        qrow[k] = (int8_t)max(-127, min(127, q));
    }
}

__global__ void k_build_patches(const float* __restrict__ image) {
    int p = blockIdx.x;
    __shared__ float srow[KDIM];
    __shared__ float redm[256];
    float* prow = g_Pf + (size_t)p * KDIM;
    int8_t* qrow = g_Pq + (size_t)p * KDIM;
    int ph = p / LW_C, pw = p % LW_C;
    bool valid = (p < NPATCH);
    float mx = 0.0f;
    for (int e = threadIdx.x; e < KDIM; e += 256) {
        float v = 0.0f;
        if (valid) {
            int c = e >> 10, rem = e & 1023, kh = rem >> 5, kw = rem & 31;
            int iy = ph + kh - PAD_C, ix = pw + kw - PAD_C;
            if (iy >= 0 && iy < H_IMG && ix >= 0 && ix < W_IMG)
                v = image[(iy * W_IMG + ix) * 3 + c];
        }
        srow[e] = v;
        prow[e] = v;
        mx = fmaxf(mx, fabsf(v));
    }
    redm[threadIdx.x] = mx;
    __syncthreads();
    for (int o = 128; o; o >>= 1) {
        if (threadIdx.x < o) redm[threadIdx.x] = fmaxf(redm[threadIdx.x], redm[threadIdx.x + o]);
        __syncthreads();
    }
    float mabs = redm[0];
    float inv = (mabs > 0.0f) ? (127.0f / mabs) : 0.0f;
    if (threadIdx.x == 0) g_psc[p] = mabs / 127.0f;
    for (int e = threadIdx.x; e < KDIM; e += 256) {
        int q = __float2int_rn(srow[e] * inv);
        qrow[e] = (int8_t)max(-127, min(127, q));
    }
}

// ---- GEMM: obj[p][j] = msq[j] - 2*sp*sj*<q_p,q_j>; also per-row min ----
// CTA tile 128x256x128(int8), warp tile 64x64, 8 warps, 3-stage cp.async,
// XOR-swizzled 128B rows, fragment double-buffering (4 k32 groups / iter).
__global__ void __launch_bounds__(256) k_gemm() {
    extern __shared__ char smem[];
    const uint32_t sb = smem_u32(smem);
    const int tid = threadIdx.x;
    const int lane = tid & 31, wid = tid >> 5;
    const int wm = wid & 1, wn = wid >> 1;          // 2(M) x 4(N)
    const int mtile = blockIdx.x, ntile = blockIdx.y;

    const char* Ag = (const char*)g_Pq + (size_t)mtile * 128 * ROWB;
    const char* Bg = (const char*)g_Mq + (size_t)ntile * 256 * ROWB;

    // cp.async mapping: thread -> chunk c = tid&7 (16B), base row rb = tid>>3.
    // row_i = rb + i*32 (A i<4, B i<8). Swizzled chunk constant per thread.
    const int cch = tid & 7, rb = tid >> 3;
    const uint32_t scoff = (uint32_t)(((cch ^ (rb & 7)) * 16));
    const uint32_t gcoff = (uint32_t)(cch * 16);

    // ldsm row byte-offsets (row*128) and per-lane swizzle xor
    const int lrow = lane & 15, hi = lane >> 4, lx = lane & 7;
    uint32_t aRow[4], bRow[4];
#pragma unroll
    for (int mi = 0; mi < 4; mi++) aRow[mi] = (uint32_t)((wm * 64 + mi * 16 + lrow) * 128);
#pragma unroll
    for (int np = 0; np < 4; np++) bRow[np] = (uint32_t)(A_SZ + (wn * 64 + np * 16 + lrow) * 128);

    int acc[4][8][4];
#pragma unroll
    for (int mi = 0; mi < 4; mi++)
#pragma unroll
        for (int ni = 0; ni < 8; ni++)
#pragma unroll
            for (int q = 0; q < 4; q++) acc[mi][ni][q] = 0;

#define LOAD_STAGE(it)                                                              \
    do {                                                                            \
        uint32_t so = (uint32_t)(((it) % 3) * STAGE_B);                             \
        uint32_t kb = (uint32_t)((it) * BK);                                        \
        _Pragma("unroll")                                                           \
        for (int i = 0; i < 4; i++) {                                               \
            uint32_t r = (uint32_t)(rb + i * 32);                                   \
            cpa16(sb + so + r * 128 + scoff, Ag + (size_t)r * ROWB + kb + gcoff);   \
        }                                                                           \
        _Pragma("unroll")                                                           \
        for (int i = 0; i < 8; i++) {                                               \
            uint32_t r = (uint32_t)(rb + i * 32);                                   \
            cpa16(sb + so + A_SZ + r * 128 + scoff, Bg + (size_t)r * ROWB + kb + gcoff); \
        }                                                                           \
    } while (0)

#define LOAD_FRAGS(st, ks, A, B)                                                    \
    do {                                                                            \
        uint32_t chb = (uint32_t)((((ks) * 2 + hi) ^ lx) * 16);                     \
        _Pragma("unroll")                                                           \
        for (int mi = 0; mi < 4; mi++)                                              \
            ldsm_x4((st) + aRow[mi] + chb, (A)[mi][0], (A)[mi][1], (A)[mi][2], (A)[mi][3]); \
        _Pragma("unroll")                                                           \
        for (int np = 0; np < 4; np++)                                              \
            ldsm_x4((st) + bRow[np] + chb, (B)[np][0], (B)[np][1], (B)[np][2], (B)[np][3]); \
    } while (0)

    LOAD_STAGE(0); CP_COMMIT();
    LOAD_STAGE(1); CP_COMMIT();

    for (int it = 0; it < NK; ++it) {
        CP_WAIT1();            // stage `it` resident
        __syncthreads();       // all warps done with stage it-1 -> buffer reusable
        if (it + 2 < NK) LOAD_STAGE(it + 2);
        CP_COMMIT();

        const uint32_t st = sb + (uint32_t)((it % 3) * STAGE_B);
        uint32_t a[2][4][4], b[2][4][4];
        LOAD_FRAGS(st, 0, a[0], b[0]);
#pragma unroll
        for (int ks = 0; ks < 4; ks++) {
            int cur = ks & 1, nxt = cur ^ 1;
            if (ks < 3) LOAD_FRAGS(st, ks + 1, a[nxt], b[nxt]);
#pragma unroll
            for (int mi = 0; mi < 4; mi++)
#pragma unroll
                for (int ni = 0; ni < 8; ni++) {
                    int np = ni >> 1, hf = ni & 1;
                    mma_s8(acc[mi][ni][0], acc[mi][ni][1], acc[mi][ni][2], acc[mi][ni][3],
                           a[cur][mi][0], a[cur][mi][1], a[cur][mi][2], a[cur][mi][3],
                           b[cur][np][hf], b[cur][np][2 + hf]);
                }
        }
    }
    __syncthreads();

    // epilogue: dequant, store obj, per-row min via smem atomics
    float* sMsq = (float*)smem;
    float* sMsc = (float*)smem + 256;
    unsigned* sMin = (unsigned*)(smem + 2048);
    sMsq[tid] = g_msq[ntile * 256 + tid];
    sMsc[tid] = g_msc[ntile * 256 + tid];
    if (tid < 128) sMin[tid] = 0xFFFFFFFFu;
    __syncthreads();

    const int qrow = lane >> 2, qcol = (lane & 3) * 2;
#pragma unroll
    for (int mi = 0; mi < 4; mi++) {
        int rl0 = wm * 64 + mi * 16 + qrow;
        int m0 = mtile * 128 + rl0;
        float sp0 = 2.0f * g_psc[m0];
        float sp8 = 2.0f * g_psc[m0 + 8];
        float mn0 = BIGF, mn8 = BIGF;
#pragma unroll
        for (int ni = 0; ni < 8; ni++) {
            int nl = wn * 64 + ni * 8 + qcol;
            int n0 = ntile * 256 + nl;
            float sj0 = sMsc[nl], sj1 = sMsc[nl + 1];
            float2 v0, v1;
            v0.x = sMsq[nl]     - sp0 * sj0 * (float)acc[mi][ni][0];
            v0.y = sMsq[nl + 1] - sp0 * sj1 * (float)acc[mi][ni][1];
            v1.x = sMsq[nl]     - sp8 * sj0 * (float)acc[mi][ni][2];
            v1.y = sMsq[nl + 1] - sp8 * sj1 * (float)acc[mi][ni][3];
            mn0 = fminf(mn0, fminf(v0.x, v0.y));
            mn8 = fminf(mn8, fminf(v1.x, v1.y));
            *(float2*)&g_obj[(size_t)m0 * NMEM + n0]       = v0;
            *(float2*)&g_obj[(size_t)(m0 + 8) * NMEM + n0] = v1;
        }
        atomicMin(&sMin[rl0], fkey(mn0));
        atomicMin(&sMin[rl0 + 8], fkey(mn8));
    }
    __syncthreads();
    if (tid < 128) atomicMin(&g_min[mtile * 128 + tid], sMin[tid]);
#undef LOAD_STAGE
#undef LOAD_FRAGS
}

// ---- exact refine: threshold from g_min, candidates, exact fp32 dots ----
__global__ void k_refine(const float* __restrict__ mem, const int* __restrict__ mapping) {
    int p = blockIdx.x;
    __shared__ int cands[128];
    __shared__ int cnt;
    __shared__ float red[256];
    __shared__ float bestv;
    __shared__ int bestj;
    const float* orow = g_obj + (size_t)p * NMEM;

    float thr = funkey(g_min[p]) + MARGIN;
    if (threadIdx.x == 0) { cnt = 0; bestv = BIGF; bestj = 0x7FFFFFFF; }
    __syncthreads();

    for (int j = threadIdx.x; j < NMEM; j += 256) {
        if (orow[j] <= thr) {
            int pos = atomicAdd(&cnt, 1);
            if (pos < 128) cands[pos] = j;
        }
    }
    __syncthreads();
    int nc = min(cnt, 128);
    const float* prow = g_Pf + (size_t)p * KDIM;
    for (int ci = 0; ci < nc; ci++) {
        int j = cands[ci];
        const float* mrow = mem + (size_t)j * KDIM;
        float s = 0.0f;
        for (int k = threadIdx.x; k < KDIM; k += 256) s += prow[k] * mrow[k];
        red[threadIdx.x] = s;
        __syncthreads();
        for (int o = 128; o; o >>= 1) {
            if (threadIdx.x < o) red[threadIdx.x] += red[threadIdx.x + o];
            __syncthreads();
        }
        if (threadIdx.x == 0) {
            float obj = g_msq[j] - 2.0f * red[0];
            if (obj < bestv || (obj == bestv && j < bestj)) { bestv = obj; bestj = j; }
        }
        __syncthreads();
    }
    if (threadIdx.x == 0) g_row[p] = mapping[bestj];
}

__global__ void k_scatter(const float* __restrict__ mem2) {
    int p = blockIdx.x;
    int ph = p / LW_C, pw = p % LW_C;
    const float* row = mem2 + (size_t)g_row[p] * KDIM;
    for (int e = threadIdx.x; e < KDIM; e += 256) {
        int c = e >> 10, rem = e & 1023, kh = rem >> 5, kw = rem & 31;
        int y = ph + kh - PAD_C, x = pw + kw - PAD_C;
        if ((unsigned)y < 64u && (unsigned)x < 64u)
            atomicAdd(&g_outc[c * 4096 + y * 64 + x], row[e]);
    }
}

__global__ void k_final(float* __restrict__ out) {
    __shared__ float red[1024];
    int t = threadIdx.x;
    float m = -BIGF;
    for (int i = t; i < 12288; i += 1024) m = fmaxf(m, g_outc[i]);
    red[t] = m;
    __syncthreads();
    for (int o = 512; o; o >>= 1) {
        if (t < o) red[t] = fmaxf(red[t], red[t + o]);
        __syncthreads();
    }
    float mx = red[0];
    for (int i = t; i < 12288; i += 1024) {
        int c = i >> 12, rem = i & 4095, y = rem >> 6, x = rem & 63;
        out[(y * 64 + x) * 3 + c] = g_outc[i] / mx;
    }
}

// ------------------------------ launch -------------------------------------
extern "C" void kernel_launch(void* const* d_in, const int* in_sizes, int n_in,
                              void* d_out, int out_size) {
    const float* image   = (const float*)d_in[0];
    const float* mem     = (const float*)d_in[1];
    const float* mem2    = (const float*)d_in[2];
    const int*   mapping = (const int*)d_in[3];
    float* out = (float*)d_out;

    cudaFuncSetAttribute((const void*)k_gemm,
                         cudaFuncAttributeMaxDynamicSharedMemorySize, GEMM_SMEM);

    k_init<<<12, 1024>>>();
    k_prep_mem<<<NMEM, 256>>>(mem);
    k_build_patches<<<MPAD, 256>>>(image);
    dim3 gg(MPAD / 128, NMEM / 256);
    k_gemm<<<gg, 256, GEMM_SMEM>>>();
    k_refine<<<NPATCH, 256>>>(mem, mapping);
    k_scatter<<<NPATCH, 256>>>(mem2);
    k_final<<<1, 1024>>>(out);
}